// round 1
// baseline (speedup 1.0000x reference)
#include <cuda_runtime.h>
#include <cstdint>

#define BB 4
#define NN 4096
#define CC 80
#define CP1 81
#define KPRE 2000
#define NWORDS 32              // ceil(2000/64)
#define CAP 65536
#define W_IMG 1333.0f
#define H_IMG 800.0f
#define SCORE_THR 0.05f
#define MAXPER 100
#define MAX_RATIO 4.135166556742356f   // |ln(16/1000)|
#define CLS_OFFSET 1334.0f             // max(H,W)+1
#define TI 40                          // NMS rows per block

// ---------------- static scratch (no allocations allowed) ----------------
__device__ unsigned long long g_keys[BB][CAP];
__device__ int                g_count[BB];
__device__ float4             g_box[BB][KPRE];
__device__ float              g_score[BB][KPRE];
__device__ int                g_label[BB][KPRE];
__device__ unsigned long long g_mask[BB][KPRE][NWORDS];
__device__ unsigned char      g_keep[BB][KPRE];

// ---------------- 0: reset counters ----------------
__global__ void k_reset() {
    if (threadIdx.x < BB) g_count[threadIdx.x] = 0;
}

// ---------------- 1: softmax + threshold + compact candidates ----------------
// one warp per proposal row (81 logits)
__global__ void k_score(const float* __restrict__ cls) {
    int warp = (blockIdx.x * blockDim.x + threadIdx.x) >> 5;
    int lane = threadIdx.x & 31;
    if (warp >= BB * NN) return;
    int b = warp / NN;
    int n = warp % NN;
    const float* p = cls + (size_t)warp * CP1;

    float v0 = p[lane];                                    // c = lane        (0..31)
    float v1 = p[lane + 32];                               // c = lane+32     (32..63)
    float v2 = (lane + 64 < CP1) ? p[lane + 64] : -1e30f;  // c = lane+64     (64..80)

    float m = fmaxf(fmaxf(v0, v1), v2);
    #pragma unroll
    for (int o = 16; o; o >>= 1) m = fmaxf(m, __shfl_xor_sync(0xffffffffu, m, o));

    float e0 = expf(v0 - m);
    float e1 = expf(v1 - m);
    float e2 = (lane + 64 < CP1) ? expf(v2 - m) : 0.0f;
    float s = e0 + e1 + e2;
    #pragma unroll
    for (int o = 16; o; o >>= 1) s += __shfl_xor_sync(0xffffffffu, s, o);

    // classes: only c < 80 are foreground
    #pragma unroll
    for (int r = 0; r < 3; r++) {
        int c = lane + r * 32;
        float e = (r == 0) ? e0 : (r == 1) ? e1 : e2;
        if (c < CC) {
            float sc = e / s;
            if (sc > SCORE_THR) {
                int pos = atomicAdd(&g_count[b], 1);
                if (pos < CAP) {
                    unsigned int sb = __float_as_uint(sc);
                    unsigned int lo = 0xFFFFFFFFu - (unsigned int)(n * CC + c);
                    g_keys[b][pos] = ((unsigned long long)sb << 32) | (unsigned long long)lo;
                }
            }
        }
    }
}

// ---------------- 2: per-image bitonic sort (descending) ----------------
__global__ void k_sort() {
    int b = blockIdx.x;
    unsigned long long* keys = g_keys[b];
    int M = g_count[b];
    if (M > CAP) M = CAP;
    int P = 2048;                     // must cover KPRE
    while (P < M) P <<= 1;
    for (int i = M + threadIdx.x; i < P; i += blockDim.x) keys[i] = 0ULL;
    __syncthreads();
    for (int k = 2; k <= P; k <<= 1) {
        for (int j = k >> 1; j > 0; j >>= 1) {
            for (int i = threadIdx.x; i < P; i += blockDim.x) {
                int ixj = i ^ j;
                if (ixj > i) {
                    unsigned long long a = keys[i];
                    unsigned long long c = keys[ixj];
                    bool desc = ((i & k) == 0);
                    if (desc ? (a < c) : (a > c)) { keys[i] = c; keys[ixj] = a; }
                }
            }
            __syncthreads();
        }
    }
}

// ---------------- 3: decode + clip only top-2000 ----------------
__global__ void k_decode(const float* __restrict__ reg, const float* __restrict__ rois) {
    int t = blockIdx.x * blockDim.x + threadIdx.x;
    if (t >= BB * KPRE) return;
    int b = t / KPRE;
    int k = t % KPRE;
    unsigned long long key = g_keys[b][k];
    if (key == 0ULL) {
        g_box[b][k] = make_float4(0.f, 0.f, 0.f, 0.f);
        g_score[b][k] = 0.f;
        g_label[b][k] = 0;
        return;
    }
    float sc = __uint_as_float((unsigned int)(key >> 32));
    unsigned int idx = 0xFFFFFFFFu - (unsigned int)(key & 0xFFFFFFFFu);
    int n = idx / CC;
    int c = idx % CC;
    const float* r = rois + ((size_t)b * NN + n) * 4;
    float x1 = r[0], y1 = r[1], x2 = r[2], y2 = r[3];
    float px = (x1 + x2) * 0.5f;
    float py = (y1 + y2) * 0.5f;
    float pw = x2 - x1;
    float ph = y2 - y1;
    const float* d = reg + ((size_t)b * NN + n) * (4 * CC) + 4 * c;
    float dx = d[0] * 0.1f;
    float dy = d[1] * 0.1f;
    float dw = fminf(d[2] * 0.2f, MAX_RATIO);
    float dh = fminf(d[3] * 0.2f, MAX_RATIO);
    float gx = px + pw * dx;
    float gy = py + ph * dy;
    float gw = pw * expf(dw);
    float gh = ph * expf(dh);
    float bx1 = gx - gw * 0.5f, by1 = gy - gh * 0.5f;
    float bx2 = gx + gw * 0.5f, by2 = gy + gh * 0.5f;
    bx1 = fminf(fmaxf(bx1, 0.f), W_IMG);
    bx2 = fminf(fmaxf(bx2, 0.f), W_IMG);
    by1 = fminf(fmaxf(by1, 0.f), H_IMG);
    by2 = fminf(fmaxf(by2, 0.f), H_IMG);
    g_box[b][k] = make_float4(bx1, by1, bx2, by2);
    g_score[b][k] = sc;
    g_label[b][k] = c;
}

// ---------------- 4: NMS suppression bitmask ----------------
// Reference does IoU on class-offset boxes (box + label*1334). The large offset
// quantizes coords in fp32, so we reproduce that arithmetic exactly for
// same-class pairs; cross-class pairs have IoU exactly 0 (gap >= 1 px).
__global__ void k_mask() {
    __shared__ float4 sbox[KPRE];   // OFFSET boxes
    __shared__ int    slab[KPRE];
    int b = blockIdx.x;
    for (int i = threadIdx.x; i < KPRE; i += blockDim.x) {
        float4 bx = g_box[b][i];
        float off = (float)g_label[b][i] * CLS_OFFSET;
        sbox[i] = make_float4(bx.x + off, bx.y + off, bx.z + off, bx.w + off);
        slab[i] = g_label[b][i];
    }
    __syncthreads();
    const int items = TI * NWORDS;  // 1280
    for (int it = threadIdx.x; it < items; it += blockDim.x) {
        int i = blockIdx.y * TI + (it >> 5);
        int w = it & 31;
        float4 bi = sbox[i];
        int li = slab[i];
        float ai = (bi.z - bi.x) * (bi.w - bi.y);
        unsigned long long bits = 0ULL;
        int j0 = w << 6;
        int j1 = min(j0 + 64, KPRE);
        int js = max(j0, i + 1);
        for (int j = js; j < j1; j++) {
            if (slab[j] != li) continue;
            float4 bj = sbox[j];
            float xx1 = fmaxf(bi.x, bj.x);
            float yy1 = fmaxf(bi.y, bj.y);
            float xx2 = fminf(bi.z, bj.z);
            float yy2 = fminf(bi.w, bj.w);
            float iw = fmaxf(xx2 - xx1, 0.f);
            float ih = fmaxf(yy2 - yy1, 0.f);
            float inter = iw * ih;
            float aj = (bj.z - bj.x) * (bj.w - bj.y);
            float uni = fmaxf(ai + aj - inter, 1e-6f);
            float iou = inter / uni;
            if (iou > 0.5f) bits |= 1ULL << (j & 63);
        }
        g_mask[b][i][w] = bits;
    }
}

// ---------------- 5: sequential greedy scan (one warp per image) ----------------
__global__ void k_scan() {
    int b = blockIdx.x;
    int lane = threadIdx.x;  // 0..31, each lane owns one remv word
    unsigned long long remv = 0ULL;
    const unsigned long long* mask = &g_mask[b][0][0];
    for (int base = 0; base < KPRE; base += 16) {
        unsigned long long buf[16];
        #pragma unroll
        for (int r = 0; r < 16; r++) buf[r] = mask[(size_t)(base + r) * NWORDS + lane];
        float sc = (lane < 16) ? g_score[b][base + lane] : 0.f;
        unsigned int keepbits = 0;
        #pragma unroll
        for (int r = 0; r < 16; r++) {
            int i = base + r;
            unsigned long long rw = __shfl_sync(0xffffffffu, remv, i >> 6);
            float si = __shfl_sync(0xffffffffu, sc, r);
            bool keep = (((rw >> (i & 63)) & 1ULL) == 0ULL) && (si > 0.f);
            if (keep) { remv |= buf[r]; keepbits |= (1u << r); }
        }
        if (lane == 0) {
            #pragma unroll
            for (int r = 0; r < 16; r++) g_keep[b][base + r] = (keepbits >> r) & 1u;
        }
    }
}

// ---------------- 6: compact top-100, write outputs ----------------
// Output layout (float32): det_b [B,100,4] | det_s [B,100] | det_l [B,100]
__global__ void k_final(float* __restrict__ out) {
    __shared__ int sel[MAXPER];
    __shared__ int scnt;
    __shared__ unsigned char sk[KPRE];
    int b = blockIdx.x;
    for (int i = threadIdx.x; i < KPRE; i += blockDim.x) sk[i] = g_keep[b][i];
    __syncthreads();
    if (threadIdx.x == 0) {
        int c = 0;
        for (int i = 0; i < KPRE && c < MAXPER; i++)
            if (sk[i]) sel[c++] = i;
        scnt = c;
    }
    __syncthreads();
    int t = threadIdx.x;
    if (t < MAXPER) {
        float bx0 = 0.f, bx1 = 0.f, bx2 = 0.f, bx3 = 0.f;
        float sc = 0.f;
        float lb = -1.f;
        if (t < scnt) {
            int i = sel[t];
            float4 bb = g_box[b][i];
            bx0 = bb.x; bx1 = bb.y; bx2 = bb.z; bx3 = bb.w;
            sc = g_score[b][i];
            lb = (float)g_label[b][i];
        }
        float* pb = out + ((size_t)b * MAXPER + t) * 4;
        pb[0] = bx0; pb[1] = bx1; pb[2] = bx2; pb[3] = bx3;
        out[BB * MAXPER * 4 + b * MAXPER + t] = sc;
        out[BB * MAXPER * 4 + BB * MAXPER + b * MAXPER + t] = lb;
    }
}

extern "C" void kernel_launch(void* const* d_in, const int* in_sizes, int n_in,
                              void* d_out, int out_size) {
    const float* cls  = (const float*)d_in[0];   // [B,N,81]
    const float* reg  = (const float*)d_in[1];   // [B,N,320]
    const float* rois = (const float*)d_in[2];   // [B,N,4]
    float* out = (float*)d_out;

    k_reset<<<1, 32>>>();
    k_score<<<(BB * NN * 32) / 256, 256>>>(cls);
    k_sort<<<BB, 1024>>>();
    k_decode<<<(BB * KPRE + 255) / 256, 256>>>(reg, rois);
    k_mask<<<dim3(BB, KPRE / TI), 256>>>();
    k_scan<<<BB, 32>>>();
    k_final<<<BB, 256>>>(out);
}

// round 2
// speedup vs baseline: 4.9593x; 4.9593x over previous
#include <cuda_runtime.h>
#include <cstdint>

#define BB 4
#define NN 4096
#define CC 80
#define CP1 81
#define KPRE 2000
#define PAD 2048
#define CAP 65536
#define W_IMG 1333.0f
#define H_IMG 800.0f
#define SCORE_THR 0.05f
#define MAXPER 100
#define MAX_RATIO 4.135166556742356f   // |ln(16/1000)|
#define CLS_OFFSET 1334.0f             // max(H,W)+1

// ---------------- static scratch (no allocations allowed) ----------------
__device__ unsigned long long g_keys[BB][CAP];
__device__ int                g_count[BB];
__device__ unsigned long long g_top[BB][PAD];
__device__ float4             g_box[BB][KPRE];
__device__ float              g_score[BB][KPRE];
__device__ int                g_label[BB][KPRE];

// ---------------- 0: reset counters ----------------
__global__ void k_reset() {
    if (threadIdx.x < BB) g_count[threadIdx.x] = 0;
}

// ---------------- 1: softmax + threshold + compact candidates ----------------
// one warp per proposal row (81 logits); warp-aggregated atomics
__global__ void k_score(const float* __restrict__ cls) {
    int warp = (blockIdx.x * blockDim.x + threadIdx.x) >> 5;
    int lane = threadIdx.x & 31;
    if (warp >= BB * NN) return;
    int b = warp / NN;
    int n = warp % NN;
    const float* p = cls + (size_t)warp * CP1;

    float v0 = p[lane];
    float v1 = p[lane + 32];
    float v2 = (lane + 64 < CP1) ? p[lane + 64] : -1e30f;

    float m = fmaxf(fmaxf(v0, v1), v2);
    #pragma unroll
    for (int o = 16; o; o >>= 1) m = fmaxf(m, __shfl_xor_sync(0xffffffffu, m, o));

    float e0 = expf(v0 - m);
    float e1 = expf(v1 - m);
    float e2 = (lane + 64 < CP1) ? expf(v2 - m) : 0.0f;
    float s = e0 + e1 + e2;
    #pragma unroll
    for (int o = 16; o; o >>= 1) s += __shfl_xor_sync(0xffffffffu, s, o);

    #pragma unroll
    for (int r = 0; r < 3; r++) {
        int c = lane + r * 32;
        float e = (r == 0) ? e0 : (r == 1) ? e1 : e2;
        float sc = e / s;
        bool f = (c < CC) && (sc > SCORE_THR);
        unsigned bal = __ballot_sync(0xffffffffu, f);
        int cnt = __popc(bal);
        int base = 0;
        if (lane == 0 && cnt) base = atomicAdd(&g_count[b], cnt);
        base = __shfl_sync(0xffffffffu, base, 0);
        if (f) {
            int pos = base + __popc(bal & ((1u << lane) - 1));
            if (pos < CAP) {
                unsigned int sb = __float_as_uint(sc);
                unsigned int lo = 0xFFFFFFFFu - (unsigned int)(n * CC + c);
                g_keys[b][pos] = ((unsigned long long)sb << 32) | (unsigned long long)lo;
            }
        }
    }
}

// ---------------- 2: radix-select top-2000 key + compact + smem bitonic sort --
__global__ void k_select() {
    __shared__ unsigned int s_hist[256];
    __shared__ unsigned long long s_prefix;
    __shared__ int s_rank;
    __shared__ int s_cnt;
    __shared__ unsigned long long s_sel[PAD];

    int b = blockIdx.x;
    int tid = threadIdx.x;
    const unsigned long long* keys = g_keys[b];
    int M = g_count[b];
    if (M > CAP) M = CAP;

    unsigned long long T;
    if (M <= KPRE) {
        T = 1ULL;   // take everything (keys are nonzero)
    } else {
        if (tid == 0) { s_prefix = 0ULL; s_rank = KPRE; }
        __syncthreads();
        for (int level = 0; level < 8; level++) {
            int shift = 56 - 8 * level;
            unsigned long long pmask = (level == 0) ? 0ULL : (~0ULL) << (64 - 8 * level);
            if (tid < 256) s_hist[tid] = 0;
            __syncthreads();
            unsigned long long pref = s_prefix;
            for (int i = tid; i < M; i += blockDim.x) {
                unsigned long long k = keys[i];
                if ((k & pmask) == pref)
                    atomicAdd(&s_hist[(unsigned int)((k >> shift) & 0xFF)], 1u);
            }
            __syncthreads();
            if (tid < 256) {
                // cum_gt = count of keys in bins strictly above tid
                unsigned int cg = 0;
                for (int bb2 = tid + 1; bb2 < 256; bb2++) cg += s_hist[bb2];
                int rk = s_rank;
                if ((int)cg < rk && (int)(cg + s_hist[tid]) >= rk) {
                    s_prefix = pref | ((unsigned long long)tid << shift);
                    s_rank = rk - (int)cg;
                }
            }
            __syncthreads();
        }
        T = s_prefix;
    }

    // compact keys >= T
    if (tid == 0) s_cnt = 0;
    __syncthreads();
    for (int i = tid; i < M; i += blockDim.x) {
        unsigned long long k = keys[i];
        if (k >= T) {
            int pos = atomicAdd(&s_cnt, 1);
            if (pos < PAD) s_sel[pos] = k;
        }
    }
    __syncthreads();
    int cnt = s_cnt; if (cnt > PAD) cnt = PAD;
    for (int i = cnt + tid; i < PAD; i += blockDim.x) s_sel[i] = 0ULL;
    __syncthreads();

    // bitonic sort PAD keys descending, in smem
    for (int k = 2; k <= PAD; k <<= 1) {
        for (int j = k >> 1; j > 0; j >>= 1) {
            for (int i = tid; i < PAD; i += blockDim.x) {
                int ixj = i ^ j;
                if (ixj > i) {
                    unsigned long long a = s_sel[i];
                    unsigned long long c = s_sel[ixj];
                    bool desc = ((i & k) == 0);
                    if (desc ? (a < c) : (a > c)) { s_sel[i] = c; s_sel[ixj] = a; }
                }
            }
            __syncthreads();
        }
    }
    for (int i = tid; i < PAD; i += blockDim.x) g_top[b][i] = s_sel[i];
}

// ---------------- 3: decode + clip only top-2000 ----------------
__global__ void k_decode(const float* __restrict__ reg, const float* __restrict__ rois) {
    int t = blockIdx.x * blockDim.x + threadIdx.x;
    if (t >= BB * KPRE) return;
    int b = t / KPRE;
    int k = t % KPRE;
    unsigned long long key = g_top[b][k];
    if (key == 0ULL) {
        g_box[b][k] = make_float4(0.f, 0.f, 0.f, 0.f);
        g_score[b][k] = 0.f;
        g_label[b][k] = 0;
        return;
    }
    float sc = __uint_as_float((unsigned int)(key >> 32));
    unsigned int idx = 0xFFFFFFFFu - (unsigned int)(key & 0xFFFFFFFFu);
    int n = idx / CC;
    int c = idx % CC;
    const float* r = rois + ((size_t)b * NN + n) * 4;
    float x1 = r[0], y1 = r[1], x2 = r[2], y2 = r[3];
    float px = (x1 + x2) * 0.5f;
    float py = (y1 + y2) * 0.5f;
    float pw = x2 - x1;
    float ph = y2 - y1;
    const float* d = reg + ((size_t)b * NN + n) * (4 * CC) + 4 * c;
    float dx = d[0] * 0.1f;
    float dy = d[1] * 0.1f;
    float dw = fminf(d[2] * 0.2f, MAX_RATIO);
    float dh = fminf(d[3] * 0.2f, MAX_RATIO);
    float gx = px + pw * dx;
    float gy = py + ph * dy;
    float gw = pw * expf(dw);
    float gh = ph * expf(dh);
    float bx1 = gx - gw * 0.5f, by1 = gy - gh * 0.5f;
    float bx2 = gx + gw * 0.5f, by2 = gy + gh * 0.5f;
    bx1 = fminf(fmaxf(bx1, 0.f), W_IMG);
    bx2 = fminf(fmaxf(bx2, 0.f), W_IMG);
    by1 = fminf(fmaxf(by1, 0.f), H_IMG);
    by2 = fminf(fmaxf(by2, 0.f), H_IMG);
    g_box[b][k] = make_float4(bx1, by1, bx2, by2);
    g_score[b][k] = sc;
    g_label[b][k] = c;
}

// ---------------- 4: per-class parallel greedy NMS + final top-100 ----------
// class-aware NMS decomposes: suppression only couples same-class boxes and
// greedy-by-global-score restricted to a class == greedy within that class.
__global__ void k_nms_final(float* __restrict__ out) {
    __shared__ float4 s_box[KPRE];          // OFFSET boxes (exact ref arithmetic)
    __shared__ short  s_lab[KPRE];          // -1 = invalid
    __shared__ short  s_idx[KPRE];          // per-class segmented index lists
    __shared__ unsigned char s_sup[KPRE];
    __shared__ int s_ccount[CC];
    __shared__ int s_coff[CC];
    __shared__ int s_wcnt[64];
    __shared__ int s_woff[64];
    __shared__ int s_sel[MAXPER];
    __shared__ int s_scnt;

    int b = blockIdx.x;
    int tid = threadIdx.x;
    int lane = tid & 31;
    int wid = tid >> 5;

    if (tid < CC) s_ccount[tid] = 0;
    __syncthreads();

    // load, offset, classify
    for (int i = tid; i < KPRE; i += blockDim.x) {
        float sc = g_score[b][i];
        float4 bx = g_box[b][i];
        int lb = g_label[b][i];
        bool valid = sc > 0.f;
        float off = (float)lb * CLS_OFFSET;
        s_box[i] = make_float4(bx.x + off, bx.y + off, bx.z + off, bx.w + off);
        s_lab[i] = valid ? (short)lb : (short)-1;
        s_sup[i] = 0;
        if (valid) atomicAdd(&s_ccount[lb], 1);
    }
    __syncthreads();

    if (tid == 0) {
        int acc = 0;
        for (int c = 0; c < CC; c++) { s_coff[c] = acc; acc += s_ccount[c]; }
    }
    __syncthreads();

    // stable scatter: warp per class, in score (=position) order
    for (int c = wid; c < CC; c += 32) {
        int base = s_coff[c];
        int cnt = 0;
        for (int p0 = 0; p0 < KPRE; p0 += 32) {
            int p = p0 + lane;
            bool f = (p < KPRE) && (s_lab[p] == (short)c);
            unsigned bal = __ballot_sync(0xffffffffu, f);
            if (f) s_idx[base + cnt + __popc(bal & ((1u << lane) - 1))] = (short)p;
            cnt += __popc(bal);
        }
    }
    __syncthreads();

    // per-class greedy NMS (warp per class)
    for (int c = wid; c < CC; c += 32) {
        int n = s_ccount[c];
        int base = s_coff[c];
        for (int ii = 0; ii < n; ii++) {
            int pi = s_idx[base + ii];
            if (!s_sup[pi]) {
                float4 bi = s_box[pi];
                float ai = (bi.z - bi.x) * (bi.w - bi.y);
                for (int jj = ii + 1 + lane; jj < n; jj += 32) {
                    int pj = s_idx[base + jj];
                    float4 bj = s_box[pj];
                    float xx1 = fmaxf(bi.x, bj.x);
                    float yy1 = fmaxf(bi.y, bj.y);
                    float xx2 = fminf(bi.z, bj.z);
                    float yy2 = fminf(bi.w, bj.w);
                    float iw = fmaxf(xx2 - xx1, 0.f);
                    float ih = fmaxf(yy2 - yy1, 0.f);
                    float inter = iw * ih;
                    float aj = (bj.z - bj.x) * (bj.w - bj.y);
                    float uni = fmaxf(ai + aj - inter, 1e-6f);
                    if (inter / uni > 0.5f) s_sup[pj] = 1;
                }
            }
            __syncwarp();
        }
    }
    __syncthreads();

    // keep = valid && !suppressed; compact first 100 in global score order
    // stage 1: per-32-chunk counts
    for (int h = 0; h < 2; h++) {
        int t = h * 1024 + tid;
        bool f = (t < KPRE) && (s_lab[t] >= 0) && (s_sup[t] == 0);
        unsigned bal = __ballot_sync(0xffffffffu, f);
        if (lane == 0 && (t >> 5) < 64) s_wcnt[t >> 5] = __popc(bal);
    }
    __syncthreads();
    if (tid == 0) {
        int acc = 0;
        for (int w = 0; w < 63; w++) { s_woff[w] = acc; acc += s_wcnt[w]; }
        s_scnt = (acc < MAXPER) ? acc : MAXPER;
    }
    __syncthreads();
    for (int h = 0; h < 2; h++) {
        int t = h * 1024 + tid;
        bool f = (t < KPRE) && (s_lab[t] >= 0) && (s_sup[t] == 0);
        unsigned bal = __ballot_sync(0xffffffffu, f);
        if (f) {
            int pos = s_woff[t >> 5] + __popc(bal & ((1u << lane) - 1));
            if (pos < MAXPER) s_sel[pos] = t;
        }
    }
    __syncthreads();

    if (tid < MAXPER) {
        float bx0 = 0.f, bx1 = 0.f, bx2 = 0.f, bx3 = 0.f;
        float sc = 0.f, lb = -1.f;
        if (tid < s_scnt) {
            int i = s_sel[tid];
            float4 bb = g_box[b][i];
            bx0 = bb.x; bx1 = bb.y; bx2 = bb.z; bx3 = bb.w;
            sc = g_score[b][i];
            lb = (float)g_label[b][i];
        }
        float* pb = out + ((size_t)b * MAXPER + tid) * 4;
        pb[0] = bx0; pb[1] = bx1; pb[2] = bx2; pb[3] = bx3;
        out[BB * MAXPER * 4 + b * MAXPER + tid] = sc;
        out[BB * MAXPER * 4 + BB * MAXPER + b * MAXPER + tid] = lb;
    }
}

extern "C" void kernel_launch(void* const* d_in, const int* in_sizes, int n_in,
                              void* d_out, int out_size) {
    const float* cls  = (const float*)d_in[0];   // [B,N,81]
    const float* reg  = (const float*)d_in[1];   // [B,N,320]
    const float* rois = (const float*)d_in[2];   // [B,N,4]
    float* out = (float*)d_out;

    k_reset<<<1, 32>>>();
    k_score<<<(BB * NN * 32) / 256, 256>>>(cls);
    k_select<<<BB, 1024>>>();
    k_decode<<<(BB * KPRE + 255) / 256, 256>>>(reg, rois);
    k_nms_final<<<BB, 1024>>>(out);
}

// round 3
// speedup vs baseline: 5.7051x; 1.1504x over previous
#include <cuda_runtime.h>
#include <cstdint>

#define BB 4
#define NN 4096
#define CC 80
#define CP1 81
#define KPRE 2000
#define PAD 2048
#define CAP 65536
#define W_IMG 1333.0f
#define H_IMG 800.0f
#define SCORE_THR 0.05f
#define MAXPER 100
#define MAX_RATIO 4.135166556742356f   // |ln(16/1000)|
#define CLS_OFFSET 1334.0f             // max(H,W)+1

// ---------------- static scratch (no allocations allowed) ----------------
__device__ unsigned long long g_keys[BB][CAP];
__device__ int                g_count[BB];          // zero-init at load; reset by k_seldec
__device__ float4             g_box[BB][KPRE];
__device__ float              g_score[BB][KPRE];
__device__ int                g_label[BB][KPRE];

// ---------------- 1: softmax + threshold + compact candidates ----------------
// one warp per proposal row (81 logits); warp-aggregated atomics
__global__ void k_score(const float* __restrict__ cls) {
    int warp = (blockIdx.x * blockDim.x + threadIdx.x) >> 5;
    int lane = threadIdx.x & 31;
    if (warp >= BB * NN) return;
    int b = warp / NN;
    int n = warp % NN;
    const float* p = cls + (size_t)warp * CP1;

    float v0 = p[lane];
    float v1 = p[lane + 32];
    float v2 = (lane + 64 < CP1) ? p[lane + 64] : -1e30f;

    float m = fmaxf(fmaxf(v0, v1), v2);
    #pragma unroll
    for (int o = 16; o; o >>= 1) m = fmaxf(m, __shfl_xor_sync(0xffffffffu, m, o));

    float e0 = expf(v0 - m);
    float e1 = expf(v1 - m);
    float e2 = (lane + 64 < CP1) ? expf(v2 - m) : 0.0f;
    float s = e0 + e1 + e2;
    #pragma unroll
    for (int o = 16; o; o >>= 1) s += __shfl_xor_sync(0xffffffffu, s, o);

    #pragma unroll
    for (int r = 0; r < 3; r++) {
        int c = lane + r * 32;
        float e = (r == 0) ? e0 : (r == 1) ? e1 : e2;
        float sc = e / s;
        bool f = (c < CC) && (sc > SCORE_THR);
        unsigned bal = __ballot_sync(0xffffffffu, f);
        int cnt = __popc(bal);
        int base = 0;
        if (lane == 0 && cnt) base = atomicAdd(&g_count[b], cnt);
        base = __shfl_sync(0xffffffffu, base, 0);
        if (f) {
            int pos = base + __popc(bal & ((1u << lane) - 1));
            if (pos < CAP) {
                unsigned int sb = __float_as_uint(sc);
                unsigned int lo = 0xFFFFFFFFu - (unsigned int)(n * CC + c);
                g_keys[b][pos] = ((unsigned long long)sb << 32) | (unsigned long long)lo;
            }
        }
    }
}

// ------- 2: early-exit radix threshold + compact + hierarchical bitonic sort
//            + decode/clip of top-2000, all fused (one block per image) -------
__global__ void k_seldec(const float* __restrict__ reg, const float* __restrict__ rois) {
    __shared__ unsigned int       s_hist[256];
    __shared__ unsigned long long s_prefix;
    __shared__ unsigned long long s_T;
    __shared__ int s_rank, s_done, s_cnt, s_M;
    __shared__ unsigned long long s_sel[PAD];

    int b = blockIdx.x;
    int tid = threadIdx.x;
    const unsigned long long* keys = g_keys[b];

    if (tid == 0) {
        int M = g_count[b]; if (M > CAP) M = CAP;
        s_M = M;
        g_count[b] = 0;                 // reset for next graph replay
        s_prefix = 0ULL;
        s_rank = KPRE;
        s_done = (M <= KPRE) ? 1 : 0;   // take everything (keys are nonzero)
        s_T = 1ULL;
        s_cnt = 0;
    }
    __syncthreads();
    int M = s_M;

    if (!s_done) {
        for (int level = 0; level < 8; level++) {
            int shift = 56 - 8 * level;
            unsigned long long pmask = (level == 0) ? 0ULL : ((~0ULL) << (64 - 8 * level));
            if (tid < 256) s_hist[tid] = 0;
            __syncthreads();
            unsigned long long pref = s_prefix;
            for (int i = tid; i < M; i += blockDim.x) {
                unsigned long long k = keys[i];
                if ((k & pmask) == pref)
                    atomicAdd(&s_hist[(unsigned int)((k >> shift) & 0xFF)], 1u);
            }
            __syncthreads();
            if (tid < 256) {
                unsigned int cg = 0;                      // keys strictly above this bin
                for (int q = tid + 1; q < 256; q++) cg += s_hist[q];
                int rk = s_rank;
                unsigned int h = s_hist[tid];
                if ((int)cg < rk && (int)(cg + h) >= rk) {   // exactly one bin matches
                    if ((int)(cg + h) <= PAD || level == 7) {
                        // threshold at this bin's floor: yields cg+h in [rank, PAD] keys
                        s_T = pref | ((unsigned long long)tid << shift);
                        s_done = 1;
                    } else {
                        s_prefix = pref | ((unsigned long long)tid << shift);
                        s_rank = rk - (int)cg;
                    }
                }
            }
            __syncthreads();
            if (s_done) break;
        }
    }
    __syncthreads();
    unsigned long long T = s_T;

    // compact keys >= T (count in [2000, 2048] when M > KPRE, else M)
    for (int i = tid; i < M; i += blockDim.x) {
        unsigned long long k = keys[i];
        if (k >= T) {
            int pos = atomicAdd(&s_cnt, 1);
            if (pos < PAD) s_sel[pos] = k;
        }
    }
    __syncthreads();
    int cnt = s_cnt; if (cnt > PAD) cnt = PAD;
    for (int i = cnt + tid; i < PAD; i += blockDim.x) s_sel[i] = 0ULL;
    __syncthreads();

    // hierarchical bitonic sort, descending:
    //  j >= 64  : cross-chunk passes with block barriers
    //  j <= 32  : within warp-owned 64-element chunk, __syncwarp only
    int lane = tid & 31;
    int wbase = (tid >> 5) << 6;     // 32 warps x 64 elements = 2048
    for (int k = 2; k <= PAD; k <<= 1) {
        for (int j = k >> 1; j >= 64; j >>= 1) {
            #pragma unroll
            for (int i = tid; i < PAD; i += 1024) {
                int ixj = i ^ j;
                if (ixj > i) {
                    unsigned long long a = s_sel[i];
                    unsigned long long c = s_sel[ixj];
                    bool desc = ((i & k) == 0);
                    if (desc ? (a < c) : (a > c)) { s_sel[i] = c; s_sel[ixj] = a; }
                }
            }
            __syncthreads();
        }
        int j0 = ((k >> 1) < 32) ? (k >> 1) : 32;
        for (int j = j0; j >= 1; j >>= 1) {
            #pragma unroll
            for (int i = wbase + lane; i < wbase + 64; i += 32) {
                int ixj = i ^ j;
                if (ixj > i) {
                    unsigned long long a = s_sel[i];
                    unsigned long long c = s_sel[ixj];
                    bool desc = ((i & k) == 0);
                    if (desc ? (a < c) : (a > c)) { s_sel[i] = c; s_sel[ixj] = a; }
                }
            }
            __syncwarp();
        }
        if ((k << 1) > 64) __syncthreads();  // before next stage's cross-chunk pass
    }

    // decode + clip the sorted top-2000 (2 rows per thread)
    for (int k2 = tid; k2 < KPRE; k2 += blockDim.x) {
        unsigned long long key = s_sel[k2];
        if (key == 0ULL) {
            g_box[b][k2] = make_float4(0.f, 0.f, 0.f, 0.f);
            g_score[b][k2] = 0.f;
            g_label[b][k2] = 0;
            continue;
        }
        float sc = __uint_as_float((unsigned int)(key >> 32));
        unsigned int idx = 0xFFFFFFFFu - (unsigned int)(key & 0xFFFFFFFFu);
        int n = idx / CC;
        int c = idx % CC;
        const float* r = rois + ((size_t)b * NN + n) * 4;
        float x1 = r[0], y1 = r[1], x2 = r[2], y2 = r[3];
        float px = (x1 + x2) * 0.5f;
        float py = (y1 + y2) * 0.5f;
        float pw = x2 - x1;
        float ph = y2 - y1;
        const float* d = reg + ((size_t)b * NN + n) * (4 * CC) + 4 * c;
        float dx = d[0] * 0.1f;
        float dy = d[1] * 0.1f;
        float dw = fminf(d[2] * 0.2f, MAX_RATIO);
        float dh = fminf(d[3] * 0.2f, MAX_RATIO);
        float gx = px + pw * dx;
        float gy = py + ph * dy;
        float gw = pw * expf(dw);
        float gh = ph * expf(dh);
        float bx1 = gx - gw * 0.5f, by1 = gy - gh * 0.5f;
        float bx2 = gx + gw * 0.5f, by2 = gy + gh * 0.5f;
        bx1 = fminf(fmaxf(bx1, 0.f), W_IMG);
        bx2 = fminf(fmaxf(bx2, 0.f), W_IMG);
        by1 = fminf(fmaxf(by1, 0.f), H_IMG);
        by2 = fminf(fmaxf(by2, 0.f), H_IMG);
        g_box[b][k2] = make_float4(bx1, by1, bx2, by2);
        g_score[b][k2] = sc;
        g_label[b][k2] = c;
    }
}

// ---------------- 3: per-class parallel greedy NMS + final top-100 ----------
// class-aware NMS decomposes: suppression only couples same-class boxes and
// greedy-by-global-score restricted to a class == greedy within that class.
__global__ void k_nms_final(float* __restrict__ out) {
    __shared__ float4 s_box[KPRE];          // OFFSET boxes (exact ref arithmetic)
    __shared__ short  s_lab[KPRE];          // -1 = invalid
    __shared__ short  s_idx[KPRE];          // per-class segmented index lists
    __shared__ unsigned char s_sup[KPRE];
    __shared__ int s_ccount[CC];
    __shared__ int s_coff[CC];
    __shared__ int s_wcnt[64];
    __shared__ int s_woff[64];
    __shared__ int s_sel[MAXPER];
    __shared__ int s_scnt;

    int b = blockIdx.x;
    int tid = threadIdx.x;
    int lane = tid & 31;
    int wid = tid >> 5;

    if (tid < CC) s_ccount[tid] = 0;
    __syncthreads();

    // load, offset, classify
    for (int i = tid; i < KPRE; i += blockDim.x) {
        float sc = g_score[b][i];
        float4 bx = g_box[b][i];
        int lb = g_label[b][i];
        bool valid = sc > 0.f;
        float off = (float)lb * CLS_OFFSET;
        s_box[i] = make_float4(bx.x + off, bx.y + off, bx.z + off, bx.w + off);
        s_lab[i] = valid ? (short)lb : (short)-1;
        s_sup[i] = 0;
        if (valid) atomicAdd(&s_ccount[lb], 1);
    }
    __syncthreads();

    if (tid == 0) {
        int acc = 0;
        for (int c = 0; c < CC; c++) { s_coff[c] = acc; acc += s_ccount[c]; }
    }
    __syncthreads();

    // stable scatter: warp per class, in score (=position) order
    for (int c = wid; c < CC; c += 32) {
        int base = s_coff[c];
        int cnt = 0;
        for (int p0 = 0; p0 < KPRE; p0 += 32) {
            int p = p0 + lane;
            bool f = (p < KPRE) && (s_lab[p] == (short)c);
            unsigned bal = __ballot_sync(0xffffffffu, f);
            if (f) s_idx[base + cnt + __popc(bal & ((1u << lane) - 1))] = (short)p;
            cnt += __popc(bal);
        }
    }
    __syncthreads();

    // per-class greedy NMS (warp per class)
    for (int c = wid; c < CC; c += 32) {
        int n = s_ccount[c];
        int base = s_coff[c];
        for (int ii = 0; ii < n; ii++) {
            int pi = s_idx[base + ii];
            if (!s_sup[pi]) {
                float4 bi = s_box[pi];
                float ai = (bi.z - bi.x) * (bi.w - bi.y);
                for (int jj = ii + 1 + lane; jj < n; jj += 32) {
                    int pj = s_idx[base + jj];
                    float4 bj = s_box[pj];
                    float xx1 = fmaxf(bi.x, bj.x);
                    float yy1 = fmaxf(bi.y, bj.y);
                    float xx2 = fminf(bi.z, bj.z);
                    float yy2 = fminf(bi.w, bj.w);
                    float iw = fmaxf(xx2 - xx1, 0.f);
                    float ih = fmaxf(yy2 - yy1, 0.f);
                    float inter = iw * ih;
                    float aj = (bj.z - bj.x) * (bj.w - bj.y);
                    float uni = fmaxf(ai + aj - inter, 1e-6f);
                    if (inter / uni > 0.5f) s_sup[pj] = 1;
                }
            }
            __syncwarp();
        }
    }
    __syncthreads();

    // keep = valid && !suppressed; compact first 100 in global score order
    for (int h = 0; h < 2; h++) {
        int t = h * 1024 + tid;
        bool f = (t < KPRE) && (s_lab[t] >= 0) && (s_sup[t] == 0);
        unsigned bal = __ballot_sync(0xffffffffu, f);
        if (lane == 0 && (t >> 5) < 64) s_wcnt[t >> 5] = __popc(bal);
    }
    __syncthreads();
    if (tid == 0) {
        int acc = 0;
        for (int w = 0; w < 63; w++) { s_woff[w] = acc; acc += s_wcnt[w]; }
        s_scnt = (acc < MAXPER) ? acc : MAXPER;
    }
    __syncthreads();
    for (int h = 0; h < 2; h++) {
        int t = h * 1024 + tid;
        bool f = (t < KPRE) && (s_lab[t] >= 0) && (s_sup[t] == 0);
        unsigned bal = __ballot_sync(0xffffffffu, f);
        if (f) {
            int pos = s_woff[t >> 5] + __popc(bal & ((1u << lane) - 1));
            if (pos < MAXPER) s_sel[pos] = t;
        }
    }
    __syncthreads();

    if (tid < MAXPER) {
        float bx0 = 0.f, bx1 = 0.f, bx2 = 0.f, bx3 = 0.f;
        float sc = 0.f, lb = -1.f;
        if (tid < s_scnt) {
            int i = s_sel[tid];
            float4 bb = g_box[b][i];
            bx0 = bb.x; bx1 = bb.y; bx2 = bb.z; bx3 = bb.w;
            sc = g_score[b][i];
            lb = (float)g_label[b][i];
        }
        float* pb = out + ((size_t)b * MAXPER + tid) * 4;
        pb[0] = bx0; pb[1] = bx1; pb[2] = bx2; pb[3] = bx3;
        out[BB * MAXPER * 4 + b * MAXPER + tid] = sc;
        out[BB * MAXPER * 4 + BB * MAXPER + b * MAXPER + tid] = lb;
    }
}

extern "C" void kernel_launch(void* const* d_in, const int* in_sizes, int n_in,
                              void* d_out, int out_size) {
    const float* cls  = (const float*)d_in[0];   // [B,N,81]
    const float* reg  = (const float*)d_in[1];   // [B,N,320]
    const float* rois = (const float*)d_in[2];   // [B,N,4]
    float* out = (float*)d_out;

    k_score<<<(BB * NN * 32) / 256, 256>>>(cls);
    k_seldec<<<BB, 1024>>>(reg, rois);
    k_nms_final<<<BB, 1024>>>(out);
}

// round 5
// speedup vs baseline: 6.0966x; 1.0686x over previous
#include <cuda_runtime.h>
#include <cstdint>

#define BB 4
#define NN 4096
#define CC 80
#define CP1 81
#define KPRE 2000
#define PAD 2048
#define CAP 65536
#define W_IMG 1333.0f
#define H_IMG 800.0f
#define SCORE_THR 0.05f
#define MAXPER 100
#define MAX_RATIO 4.135166556742356f   // |ln(16/1000)|
#define CLS_OFFSET 1334.0f             // max(H,W)+1

// ---------------- static scratch (no allocations allowed) ----------------
__device__ unsigned long long g_keys[BB][CAP];
__device__ int                g_count[BB];          // zero-init at load; reset by k_seldec
__device__ float4             g_box[BB][KPRE];
__device__ float              g_score[BB][KPRE];
__device__ int                g_label[BB][KPRE];

// ---------------- 1: softmax + threshold + compact candidates ----------------
// 8 lanes per proposal row: 11 independent expf per lane for ILP, 3-shfl reductions
__global__ void k_score(const float* __restrict__ cls) {
    int tid = blockIdx.x * blockDim.x + threadIdx.x;
    int row = tid >> 3;                  // global proposal row
    int o = tid & 7;                     // lane within octet
    int lane = threadIdx.x & 31;
    if (row >= BB * NN) return;
    int b = row / NN;
    int n = row % NN;
    const float* p = cls + (size_t)row * CP1;

    float v[11];
    #pragma unroll
    for (int k = 0; k < 10; k++) v[k] = p[o + 8 * k];
    v[10] = (o == 0) ? p[80] : -1e30f;   // background logit (one lane of octet)

    float m = v[0];
    #pragma unroll
    for (int k = 1; k < 11; k++) m = fmaxf(m, v[k]);
    #pragma unroll
    for (int off = 4; off; off >>= 1) m = fmaxf(m, __shfl_xor_sync(0xffffffffu, m, off));

    float e[11];
    float s = 0.f;
    #pragma unroll
    for (int k = 0; k < 11; k++) { e[k] = expf(v[k] - m); s += e[k]; }
    #pragma unroll
    for (int off = 4; off; off >>= 1) s += __shfl_xor_sync(0xffffffffu, s, off);

    // candidates: k=0..9 -> c = o + 8k in [0,80) (all foreground)
    float sc[10];
    int pass = 0, cnt = 0;
    #pragma unroll
    for (int k = 0; k < 10; k++) {
        sc[k] = e[k] / s;
        if (sc[k] > SCORE_THR) { pass |= (1 << k); cnt++; }
    }

    // warp-wide exclusive prefix of counts, single atomic per warp
    int pre = cnt;
    #pragma unroll
    for (int off = 1; off < 32; off <<= 1) {
        int t = __shfl_up_sync(0xffffffffu, pre, off);
        if (lane >= off) pre += t;
    }
    int excl = pre - cnt;
    int tot = __shfl_sync(0xffffffffu, pre, 31);
    int base = 0;
    if (lane == 0 && tot) base = atomicAdd(&g_count[b], tot);
    base = __shfl_sync(0xffffffffu, base, 0);

    int w = 0;
    #pragma unroll
    for (int k = 0; k < 10; k++) {
        if (pass & (1 << k)) {
            int pos = base + excl + w; w++;
            if (pos < CAP) {
                int c = o + 8 * k;
                unsigned int sb = __float_as_uint(sc[k]);
                unsigned int lo = 0xFFFFFFFFu - (unsigned int)(n * CC + c);
                g_keys[b][pos] = ((unsigned long long)sb << 32) | (unsigned long long)lo;
            }
        }
    }
}

// ------- 2: radix threshold (11-bit first level, exact slack bookkeeping)
//            + compact + hierarchical bitonic sort + decode of top-2000 -------
__global__ void k_seldec(const float* __restrict__ reg, const float* __restrict__ rois) {
    __shared__ unsigned int       s_hist[2048];
    __shared__ unsigned long long s_prefix;
    __shared__ unsigned long long s_T;
    __shared__ int s_above, s_done, s_cnt, s_M;
    __shared__ int s_bin, s_binh, s_bincg;
    __shared__ unsigned long long s_sel[PAD];

    int b = blockIdx.x;
    int tid = threadIdx.x;
    int lane = tid & 31;
    int wid = tid >> 5;
    const unsigned long long* keys = g_keys[b];

    if (tid == 0) {
        int M = g_count[b]; if (M > CAP) M = CAP;
        s_M = M;
        g_count[b] = 0;                 // reset for next graph replay
        s_prefix = 0ULL;
        s_above = 0;
        s_done = (M <= PAD) ? 1 : 0;    // small M: take everything (keys nonzero)
        s_T = 1ULL;
        s_cnt = 0;
    }
    __syncthreads();
    int M = s_M;

    // radix descent: level 0 = bits[63:53] (2048 bins), deeper = 8-bit fields.
    // terminates: at shift 5 a bin holds <=32 unique keys so accept fires.
    for (int level = 0; level < 7 && !s_done; level++) {
        int shift = (level == 0) ? 53 : (53 - 8 * level);
        int NB = (level == 0) ? 2048 : 256;
        unsigned long long pmask = (level == 0) ? 0ULL : ((~0ULL) << (shift + 8));
        for (int i = tid; i < NB; i += blockDim.x) s_hist[i] = 0;
        __syncthreads();
        unsigned long long pref = s_prefix;
        for (int i = tid; i < M; i += blockDim.x) {
            unsigned long long k = keys[i];
            if ((k & pmask) == pref)
                atomicAdd(&s_hist[(unsigned int)(k >> shift) & (NB - 1)], 1u);
        }
        __syncthreads();
        // single-warp suffix scan + straddle walk
        if (wid == 0) {
            int bpl = NB >> 5;                   // bins per lane
            int bb0 = lane * bpl;
            unsigned int sum = 0;
            for (int j = 0; j < bpl; j++) sum += s_hist[bb0 + j];
            unsigned int suf = sum;              // inclusive suffix over lanes
            #pragma unroll
            for (int off = 16; off; off >>= 1) {
                unsigned int t = __shfl_down_sync(0xffffffffu, suf, off);
                if (lane + off < 32) suf += t;
            }
            int above = s_above;
            unsigned int cg = suf - sum;         // keys in higher lanes
            for (int j = bpl - 1; j >= 0; j--) { // walk bins from top
                unsigned int h = s_hist[bb0 + j];
                int a = above + (int)cg;
                if (h && a < KPRE && a + (int)h >= KPRE) {
                    s_bin = bb0 + j; s_binh = (int)h; s_bincg = a;
                }
                cg += h;
            }
        }
        __syncthreads();
        if (tid == 0) {
            int a = s_bincg, h = s_binh;
            unsigned long long binv = (unsigned long long)s_bin << shift;
            if (a + h <= PAD) {                  // total taken = a+h in [2000,2048]
                s_T = s_prefix | binv;
                s_done = 1;
            } else {
                s_prefix = s_prefix | binv;
                s_above = a;
            }
        }
        __syncthreads();
    }
    unsigned long long T = s_T;

    // warp-aggregated compact of keys >= T  (UNIFORM trip count: ballot-safe)
    {
        int iters = (M + 1023) >> 10;
        for (int it = 0; it < iters; it++) {
            int i = (it << 10) + tid;
            unsigned long long k = (i < M) ? keys[i] : 0ULL;
            bool f = (i < M) && (k >= T);
            unsigned bal = __ballot_sync(0xffffffffu, f);
            int cnt = __popc(bal);
            int base = 0;
            if (lane == 0 && cnt) base = atomicAdd(&s_cnt, cnt);
            base = __shfl_sync(0xffffffffu, base, 0);
            if (f) s_sel[base + __popc(bal & ((1u << lane) - 1))] = k;
        }
    }
    __syncthreads();
    int cnt = s_cnt;
    for (int i = cnt + tid; i < PAD; i += blockDim.x) s_sel[i] = 0ULL;
    __syncthreads();

    // hierarchical bitonic sort, descending
    int wbase = wid << 6;                // 32 warps x 64-element chunks
    for (int k = 2; k <= PAD; k <<= 1) {
        for (int j = k >> 1; j >= 64; j >>= 1) {
            #pragma unroll
            for (int i = tid; i < PAD; i += 1024) {
                int ixj = i ^ j;
                if (ixj > i) {
                    unsigned long long a = s_sel[i];
                    unsigned long long c = s_sel[ixj];
                    bool desc = ((i & k) == 0);
                    if (desc ? (a < c) : (a > c)) { s_sel[i] = c; s_sel[ixj] = a; }
                }
            }
            __syncthreads();
        }
        int j0 = ((k >> 1) < 32) ? (k >> 1) : 32;
        for (int j = j0; j >= 1; j >>= 1) {
            #pragma unroll
            for (int i = wbase + lane; i < wbase + 64; i += 32) {
                int ixj = i ^ j;
                if (ixj > i) {
                    unsigned long long a = s_sel[i];
                    unsigned long long c = s_sel[ixj];
                    bool desc = ((i & k) == 0);
                    if (desc ? (a < c) : (a > c)) { s_sel[i] = c; s_sel[ixj] = a; }
                }
            }
            __syncwarp();
        }
        if ((k << 1) > 64) __syncthreads();
    }

    // decode + clip the sorted top-2000
    for (int k2 = tid; k2 < KPRE; k2 += blockDim.x) {
        unsigned long long key = s_sel[k2];
        if (key == 0ULL) {
            g_box[b][k2] = make_float4(0.f, 0.f, 0.f, 0.f);
            g_score[b][k2] = 0.f;
            g_label[b][k2] = 0;
            continue;
        }
        float sc = __uint_as_float((unsigned int)(key >> 32));
        unsigned int idx = 0xFFFFFFFFu - (unsigned int)(key & 0xFFFFFFFFu);
        int n = idx / CC;
        int c = idx % CC;
        const float* r = rois + ((size_t)b * NN + n) * 4;
        float x1 = r[0], y1 = r[1], x2 = r[2], y2 = r[3];
        float px = (x1 + x2) * 0.5f;
        float py = (y1 + y2) * 0.5f;
        float pw = x2 - x1;
        float ph = y2 - y1;
        const float* d = reg + ((size_t)b * NN + n) * (4 * CC) + 4 * c;
        float dx = d[0] * 0.1f;
        float dy = d[1] * 0.1f;
        float dw = fminf(d[2] * 0.2f, MAX_RATIO);
        float dh = fminf(d[3] * 0.2f, MAX_RATIO);
        float gx = px + pw * dx;
        float gy = py + ph * dy;
        float gw = pw * expf(dw);
        float gh = ph * expf(dh);
        float bx1 = gx - gw * 0.5f, by1 = gy - gh * 0.5f;
        float bx2 = gx + gw * 0.5f, by2 = gy + gh * 0.5f;
        bx1 = fminf(fmaxf(bx1, 0.f), W_IMG);
        bx2 = fminf(fmaxf(bx2, 0.f), W_IMG);
        by1 = fminf(fmaxf(by1, 0.f), H_IMG);
        by2 = fminf(fmaxf(by2, 0.f), H_IMG);
        g_box[b][k2] = make_float4(bx1, by1, bx2, by2);
        g_score[b][k2] = sc;
        g_label[b][k2] = c;
    }
}

// ---------------- 3: per-class parallel greedy NMS + final top-100 ----------
__global__ void k_nms_final(float* __restrict__ out) {
    __shared__ float4 s_box[KPRE];          // OFFSET boxes (exact ref arithmetic)
    __shared__ short  s_lab[KPRE];          // -1 = invalid
    __shared__ short  s_idx[KPRE];          // per-class segmented index lists
    __shared__ unsigned char s_sup[KPRE];
    __shared__ int s_ccount[CC];
    __shared__ int s_coff[CC];
    __shared__ int s_wcnt[64];
    __shared__ int s_woff[64];
    __shared__ int s_sel[MAXPER];
    __shared__ int s_scnt;

    int b = blockIdx.x;
    int tid = threadIdx.x;
    int lane = tid & 31;
    int wid = tid >> 5;

    if (tid < CC) s_ccount[tid] = 0;
    __syncthreads();

    for (int i = tid; i < KPRE; i += blockDim.x) {
        float sc = g_score[b][i];
        float4 bx = g_box[b][i];
        int lb = g_label[b][i];
        bool valid = sc > 0.f;
        float off = (float)lb * CLS_OFFSET;
        s_box[i] = make_float4(bx.x + off, bx.y + off, bx.z + off, bx.w + off);
        s_lab[i] = valid ? (short)lb : (short)-1;
        s_sup[i] = 0;
        if (valid) atomicAdd(&s_ccount[lb], 1);
    }
    __syncthreads();

    if (tid == 0) {
        int acc = 0;
        for (int c = 0; c < CC; c++) { s_coff[c] = acc; acc += s_ccount[c]; }
    }
    __syncthreads();

    // stable scatter: warp per class, in score (=position) order
    for (int c = wid; c < CC; c += 32) {
        int base = s_coff[c];
        int cnt = 0;
        for (int p0 = 0; p0 < KPRE; p0 += 32) {
            int p = p0 + lane;
            bool f = (p < KPRE) && (s_lab[p] == (short)c);
            unsigned bal = __ballot_sync(0xffffffffu, f);
            if (f) s_idx[base + cnt + __popc(bal & ((1u << lane) - 1))] = (short)p;
            cnt += __popc(bal);
        }
    }
    __syncthreads();

    // per-class greedy NMS (warp per class)
    for (int c = wid; c < CC; c += 32) {
        int n = s_ccount[c];
        int base = s_coff[c];
        for (int ii = 0; ii < n; ii++) {
            int pi = s_idx[base + ii];
            if (!s_sup[pi]) {
                float4 bi = s_box[pi];
                float ai = (bi.z - bi.x) * (bi.w - bi.y);
                for (int jj = ii + 1 + lane; jj < n; jj += 32) {
                    int pj = s_idx[base + jj];
                    float4 bj = s_box[pj];
                    float xx1 = fmaxf(bi.x, bj.x);
                    float yy1 = fmaxf(bi.y, bj.y);
                    float xx2 = fminf(bi.z, bj.z);
                    float yy2 = fminf(bi.w, bj.w);
                    float iw = fmaxf(xx2 - xx1, 0.f);
                    float ih = fmaxf(yy2 - yy1, 0.f);
                    float inter = iw * ih;
                    float aj = (bj.z - bj.x) * (bj.w - bj.y);
                    float uni = fmaxf(ai + aj - inter, 1e-6f);
                    if (inter / uni > 0.5f) s_sup[pj] = 1;
                }
            }
            __syncwarp();
        }
    }
    __syncthreads();

    // keep = valid && !suppressed; compact first 100 in global score order
    for (int h = 0; h < 2; h++) {
        int t = h * 1024 + tid;
        bool f = (t < KPRE) && (s_lab[t] >= 0) && (s_sup[t] == 0);
        unsigned bal = __ballot_sync(0xffffffffu, f);
        if (lane == 0 && (t >> 5) < 64) s_wcnt[t >> 5] = __popc(bal);
    }
    __syncthreads();
    if (tid == 0) {
        int acc = 0;
        for (int w = 0; w < 63; w++) { s_woff[w] = acc; acc += s_wcnt[w]; }
        s_scnt = (acc < MAXPER) ? acc : MAXPER;
    }
    __syncthreads();
    for (int h = 0; h < 2; h++) {
        int t = h * 1024 + tid;
        bool f = (t < KPRE) && (s_lab[t] >= 0) && (s_sup[t] == 0);
        unsigned bal = __ballot_sync(0xffffffffu, f);
        if (f) {
            int pos = s_woff[t >> 5] + __popc(bal & ((1u << lane) - 1));
            if (pos < MAXPER) s_sel[pos] = t;
        }
    }
    __syncthreads();

    if (tid < MAXPER) {
        float bx0 = 0.f, bx1 = 0.f, bx2 = 0.f, bx3 = 0.f;
        float sc = 0.f, lb = -1.f;
        if (tid < s_scnt) {
            int i = s_sel[tid];
            float4 bb = g_box[b][i];
            bx0 = bb.x; bx1 = bb.y; bx2 = bb.z; bx3 = bb.w;
            sc = g_score[b][i];
            lb = (float)g_label[b][i];
        }
        float* pb = out + ((size_t)b * MAXPER + tid) * 4;
        pb[0] = bx0; pb[1] = bx1; pb[2] = bx2; pb[3] = bx3;
        out[BB * MAXPER * 4 + b * MAXPER + tid] = sc;
        out[BB * MAXPER * 4 + BB * MAXPER + b * MAXPER + tid] = lb;
    }
}

extern "C" void kernel_launch(void* const* d_in, const int* in_sizes, int n_in,
                              void* d_out, int out_size) {
    const float* cls  = (const float*)d_in[0];   // [B,N,81]
    const float* reg  = (const float*)d_in[1];   // [B,N,320]
    const float* rois = (const float*)d_in[2];   // [B,N,4]
    float* out = (float*)d_out;

    k_score<<<(BB * NN * 8) / 256, 256>>>(cls);
    k_seldec<<<BB, 1024>>>(reg, rois);
    k_nms_final<<<BB, 1024>>>(out);
}

// round 6
// speedup vs baseline: 9.8038x; 1.6081x over previous
#include <cuda_runtime.h>
#include <cstdint>

#define BB 4
#define NN 4096
#define CC 80
#define CP1 81
#define KPRE 2000
#define CAP 65536
#define CAPC 1024              // per-class bucket cap (expected ~120/class)
#define NMSCAP 1024            // per-class NMS pool cap (expected ~25/class)
#define PADF 256               // final-stage sort width (>= 100 + bin slack)
#define W_IMG 1333.0f
#define H_IMG 800.0f
#define SCORE_THR 0.05f
#define MAXPER 100
#define MAX_RATIO 4.135166556742356f   // |ln(16/1000)|
#define CLS_OFFSET 1334.0f             // max(H,W)+1

// ---------------- static scratch (no allocations allowed) ----------------
__device__ unsigned long long g_keys[BB][CAP];          // flat candidate keys
__device__ int                g_count[BB];              // reset by k_thresh
__device__ unsigned long long g_ckeys[BB][CC][CAPC];    // per-class buckets
__device__ int                g_ccnt[BB][CC];           // reset by k_nms
__device__ unsigned long long g_T[BB];                  // exact rank-2000 threshold
__device__ unsigned long long g_skey[BB][KPRE];         // survivor keys
__device__ float4             g_sbox[BB][KPRE];         // survivor boxes (raw clipped)
__device__ int                g_scnt[BB];               // reset by k_final

// ---------------- 1: softmax + threshold + compact + bucket -----------------
__global__ void k_score(const float* __restrict__ cls) {
    int tid = blockIdx.x * blockDim.x + threadIdx.x;
    int row = tid >> 3;
    int o = tid & 7;
    int lane = threadIdx.x & 31;
    if (row >= BB * NN) return;
    int b = row / NN;
    int n = row % NN;
    const float* p = cls + (size_t)row * CP1;

    float v[11];
    #pragma unroll
    for (int k = 0; k < 10; k++) v[k] = p[o + 8 * k];
    v[10] = (o == 0) ? p[80] : -1e30f;

    float m = v[0];
    #pragma unroll
    for (int k = 1; k < 11; k++) m = fmaxf(m, v[k]);
    #pragma unroll
    for (int off = 4; off; off >>= 1) m = fmaxf(m, __shfl_xor_sync(0xffffffffu, m, off));

    float e[11];
    float s = 0.f;
    #pragma unroll
    for (int k = 0; k < 11; k++) { e[k] = expf(v[k] - m); s += e[k]; }
    #pragma unroll
    for (int off = 4; off; off >>= 1) s += __shfl_xor_sync(0xffffffffu, s, off);

    float sc[10];
    int pass = 0, cnt = 0;
    #pragma unroll
    for (int k = 0; k < 10; k++) {
        sc[k] = e[k] / s;
        if (sc[k] > SCORE_THR) { pass |= (1 << k); cnt++; }
    }

    // flat list: warp-aggregated atomic
    int pre = cnt;
    #pragma unroll
    for (int off = 1; off < 32; off <<= 1) {
        int t = __shfl_up_sync(0xffffffffu, pre, off);
        if (lane >= off) pre += t;
    }
    int excl = pre - cnt;
    int tot = __shfl_sync(0xffffffffu, pre, 31);
    int base = 0;
    if (lane == 0 && tot) base = atomicAdd(&g_count[b], tot);
    base = __shfl_sync(0xffffffffu, base, 0);

    int w = 0;
    #pragma unroll
    for (int k = 0; k < 10; k++) {
        if (pass & (1 << k)) {
            int c = o + 8 * k;
            unsigned int sb = __float_as_uint(sc[k]);
            unsigned int lo = 0xFFFFFFFFu - (unsigned int)(n * CC + c);
            unsigned long long key = ((unsigned long long)sb << 32) | (unsigned long long)lo;
            int pos = base + excl + w; w++;
            if (pos < CAP) g_keys[b][pos] = key;
            int cp = atomicAdd(&g_ccnt[b][c], 1);
            if (cp < CAPC) g_ckeys[b][c][cp] = key;
        }
    }
}

// ---------------- 2: EXACT rank-2000 radix threshold -------------------------
// levels at shifts 53(11b),45,37,29,21,13,5(8b each),0(5b). Keys unique ->
// final level bins hold one key -> accept (above+h == KPRE) guaranteed.
__global__ void k_thresh() {
    __shared__ unsigned int       s_hist[2048];
    __shared__ unsigned long long s_prefix;
    __shared__ int s_above, s_done, s_M;
    __shared__ int s_bin, s_binh, s_bincg;

    int b = blockIdx.x;
    int tid = threadIdx.x;
    int lane = tid & 31;
    int wid = tid >> 5;
    const unsigned long long* keys = g_keys[b];

    if (tid == 0) {
        int M = g_count[b]; if (M > CAP) M = CAP;
        s_M = M;
        g_count[b] = 0;
        s_prefix = 0ULL;
        s_above = 0;
        if (M <= KPRE) { g_T[b] = 1ULL; s_done = 1; } else s_done = 0;
    }
    __syncthreads();
    int M = s_M;

    for (int level = 0; level < 8 && !s_done; level++) {
        int shift = (level == 0) ? 53 : (level == 7) ? 0 : (53 - 8 * level);
        int width = (level == 0) ? 11 : (level == 7) ? 5 : 8;
        int NB = 1 << width;
        unsigned long long pmask = (level == 0) ? 0ULL : ((~0ULL) << (shift + width));
        for (int i = tid; i < NB; i += blockDim.x) s_hist[i] = 0;
        __syncthreads();
        unsigned long long pref = s_prefix;
        for (int i = tid; i < M; i += blockDim.x) {
            unsigned long long k = keys[i];
            if ((k & pmask) == pref)
                atomicAdd(&s_hist[(unsigned int)(k >> shift) & (NB - 1)], 1u);
        }
        __syncthreads();
        if (wid == 0) {
            int bpl = NB >> 5;
            int bb0 = lane * bpl;
            unsigned int sum = 0;
            for (int j = 0; j < bpl; j++) sum += s_hist[bb0 + j];
            unsigned int suf = sum;
            #pragma unroll
            for (int off = 16; off; off >>= 1) {
                unsigned int t = __shfl_down_sync(0xffffffffu, suf, off);
                if (lane + off < 32) suf += t;
            }
            int above = s_above;
            unsigned int cg = suf - sum;
            for (int j = bpl - 1; j >= 0; j--) {
                unsigned int h = s_hist[bb0 + j];
                int a = above + (int)cg;
                if (h && a < KPRE && a + (int)h >= KPRE) {
                    s_bin = bb0 + j; s_binh = (int)h; s_bincg = a;
                }
                cg += h;
            }
        }
        __syncthreads();
        if (tid == 0) {
            int a = s_bincg, h = s_binh;
            unsigned long long binv = (unsigned long long)s_bin << shift;
            if (a + h == KPRE) {                 // exact boundary: done
                g_T[b] = s_prefix | binv;
                s_done = 1;
            } else {
                s_prefix = s_prefix | binv;
                s_above = a;
            }
        }
        __syncthreads();
    }
}

// ---------------- 3: per-class NMS, one block per (class, image) -------------
__global__ void k_nms(const float* __restrict__ reg, const float* __restrict__ rois) {
    __shared__ unsigned long long s_k[NMSCAP];
    __shared__ float4             s_bx[NMSCAP];
    __shared__ unsigned char      s_sup[NMSCAP];
    __shared__ short              s_keep[NMSCAP];
    __shared__ int s_cnt, s_n, s_nk, s_base;

    int c = blockIdx.x;
    int b = blockIdx.y;
    int tid = threadIdx.x;
    int lane = tid & 31;

    if (tid == 0) {
        int cc = g_ccnt[b][c]; if (cc > CAPC) cc = CAPC;
        s_cnt = cc;
        g_ccnt[b][c] = 0;               // reset for next replay
        s_n = 0; s_nk = 0; s_base = 0;
    }
    __syncthreads();
    int cnt = s_cnt;
    unsigned long long T = g_T[b];

    // filter >= T, warp-aggregated append (uniform trips from shared cnt)
    int iters = (cnt + 127) >> 7;
    for (int it = 0; it < iters; it++) {
        int i = (it << 7) + tid;
        unsigned long long k = (i < cnt) ? g_ckeys[b][c][i] : 0ULL;
        bool f = (i < cnt) && (k >= T);
        unsigned bal = __ballot_sync(0xffffffffu, f);
        int wc = __popc(bal);
        int base = 0;
        if (lane == 0 && wc) base = atomicAdd(&s_n, wc);
        base = __shfl_sync(0xffffffffu, base, 0);
        if (f) {
            int pos = base + __popc(bal & ((1u << lane) - 1));
            if (pos < NMSCAP) s_k[pos] = k;
        }
    }
    __syncthreads();
    int n = s_n; if (n > NMSCAP) n = NMSCAP;

    // pad to pow2 and bitonic sort descending (within-class score order)
    int p = 2; while (p < n) p <<= 1;
    for (int i = n + tid; i < p; i += blockDim.x) s_k[i] = 0ULL;
    __syncthreads();
    for (int k2 = 2; k2 <= p; k2 <<= 1) {
        for (int j = k2 >> 1; j > 0; j >>= 1) {
            for (int i = tid; i < p; i += blockDim.x) {
                int ixj = i ^ j;
                if (ixj > i) {
                    unsigned long long a = s_k[i];
                    unsigned long long d = s_k[ixj];
                    bool desc = ((i & k2) == 0);
                    if (desc ? (a < d) : (a > d)) { s_k[i] = d; s_k[ixj] = a; }
                }
            }
            __syncthreads();
        }
    }

    // decode + clip
    for (int i = tid; i < n; i += blockDim.x) {
        unsigned long long key = s_k[i];
        unsigned int idx = 0xFFFFFFFFu - (unsigned int)(key & 0xFFFFFFFFu);
        int nn = idx / CC;
        const float* r = rois + ((size_t)b * NN + nn) * 4;
        float x1 = r[0], y1 = r[1], x2 = r[2], y2 = r[3];
        float px = (x1 + x2) * 0.5f;
        float py = (y1 + y2) * 0.5f;
        float pw = x2 - x1;
        float ph = y2 - y1;
        const float* d = reg + ((size_t)b * NN + nn) * (4 * CC) + 4 * c;
        float dx = d[0] * 0.1f;
        float dy = d[1] * 0.1f;
        float dw = fminf(d[2] * 0.2f, MAX_RATIO);
        float dh = fminf(d[3] * 0.2f, MAX_RATIO);
        float gx = px + pw * dx;
        float gy = py + ph * dy;
        float gw = pw * expf(dw);
        float gh = ph * expf(dh);
        float bx1 = gx - gw * 0.5f, by1 = gy - gh * 0.5f;
        float bx2 = gx + gw * 0.5f, by2 = gy + gh * 0.5f;
        bx1 = fminf(fmaxf(bx1, 0.f), W_IMG);
        bx2 = fminf(fmaxf(bx2, 0.f), W_IMG);
        by1 = fminf(fmaxf(by1, 0.f), H_IMG);
        by2 = fminf(fmaxf(by2, 0.f), H_IMG);
        s_bx[i] = make_float4(bx1, by1, bx2, by2);
        s_sup[i] = 0;
    }
    __syncthreads();

    // greedy NMS (warp 0); IoU on OFFSET boxes = exact reference arithmetic
    if (tid < 32) {
        float off = (float)c * CLS_OFFSET;
        for (int ii = 0; ii < n; ii++) {
            if (!s_sup[ii]) {
                float4 bi = s_bx[ii];
                bi.x += off; bi.y += off; bi.z += off; bi.w += off;
                float ai = (bi.z - bi.x) * (bi.w - bi.y);
                for (int jj = ii + 1 + lane; jj < n; jj += 32) {
                    float4 bj = s_bx[jj];
                    bj.x += off; bj.y += off; bj.z += off; bj.w += off;
                    float xx1 = fmaxf(bi.x, bj.x);
                    float yy1 = fmaxf(bi.y, bj.y);
                    float xx2 = fminf(bi.z, bj.z);
                    float yy2 = fminf(bi.w, bj.w);
                    float iw = fmaxf(xx2 - xx1, 0.f);
                    float ih = fmaxf(yy2 - yy1, 0.f);
                    float inter = iw * ih;
                    float aj = (bj.z - bj.x) * (bj.w - bj.y);
                    float uni = fmaxf(ai + aj - inter, 1e-6f);
                    if (inter / uni > 0.5f) s_sup[jj] = 1;
                }
            }
            __syncwarp();
        }
        if (lane == 0) {
            int mkeep = 0;
            for (int i = 0; i < n; i++)
                if (!s_sup[i]) s_keep[mkeep++] = (short)i;
            s_nk = mkeep;
            if (mkeep) s_base = atomicAdd(&g_scnt[b], mkeep);
        }
    }
    __syncthreads();
    int nk = s_nk, sb = s_base;
    for (int i = tid; i < nk; i += blockDim.x) {
        int src = s_keep[i];
        g_skey[b][sb + i] = s_k[src];
        g_sbox[b][sb + i] = s_bx[src];
    }
}

// ---------------- 4: top-100 of survivors, ordered output --------------------
__global__ void k_final(float* __restrict__ out) {
    __shared__ unsigned int       s_hist[2048];
    __shared__ unsigned long long s_prefix;
    __shared__ unsigned long long s_T;
    __shared__ int s_above, s_done, s_S, s_cnt;
    __shared__ int s_bin, s_binh, s_bincg;
    __shared__ unsigned long long s_k2[PADF];
    __shared__ short              s_slot[PADF];

    int b = blockIdx.x;
    int tid = threadIdx.x;
    int lane = tid & 31;
    int wid = tid >> 5;
    const unsigned long long* keys = g_skey[b];

    if (tid == 0) {
        int S = g_scnt[b]; if (S > KPRE) S = KPRE;
        s_S = S;
        g_scnt[b] = 0;                  // reset for next replay
        s_prefix = 0ULL;
        s_above = 0;
        s_done = (S <= PADF) ? 1 : 0;   // few survivors: take all
        s_T = 1ULL;
        s_cnt = 0;
    }
    __syncthreads();
    int S = s_S;

    // rank-100 radix with slack (a+h <= PADF); sorted cut below makes it exact
    for (int level = 0; level < 8 && !s_done; level++) {
        int shift = (level == 0) ? 53 : (level == 7) ? 0 : (53 - 8 * level);
        int width = (level == 0) ? 11 : (level == 7) ? 5 : 8;
        int NB = 1 << width;
        unsigned long long pmask = (level == 0) ? 0ULL : ((~0ULL) << (shift + width));
        for (int i = tid; i < NB; i += blockDim.x) s_hist[i] = 0;
        __syncthreads();
        unsigned long long pref = s_prefix;
        for (int i = tid; i < S; i += blockDim.x) {
            unsigned long long k = keys[i];
            if ((k & pmask) == pref)
                atomicAdd(&s_hist[(unsigned int)(k >> shift) & (NB - 1)], 1u);
        }
        __syncthreads();
        if (wid == 0) {
            int bpl = NB >> 5;
            int bb0 = lane * bpl;
            unsigned int sum = 0;
            for (int j = 0; j < bpl; j++) sum += s_hist[bb0 + j];
            unsigned int suf = sum;
            #pragma unroll
            for (int off = 16; off; off >>= 1) {
                unsigned int t = __shfl_down_sync(0xffffffffu, suf, off);
                if (lane + off < 32) suf += t;
            }
            int above = s_above;
            unsigned int cg = suf - sum;
            for (int j = bpl - 1; j >= 0; j--) {
                unsigned int h = s_hist[bb0 + j];
                int a = above + (int)cg;
                if (h && a < MAXPER && a + (int)h >= MAXPER) {
                    s_bin = bb0 + j; s_binh = (int)h; s_bincg = a;
                }
                cg += h;
            }
        }
        __syncthreads();
        if (tid == 0) {
            int a = s_bincg, h = s_binh;
            unsigned long long binv = (unsigned long long)s_bin << shift;
            if (a + h <= PADF) {            // slack accept: [100, 256] keys taken
                s_T = s_prefix | binv;
                s_done = 1;
            } else {
                s_prefix = s_prefix | binv;
                s_above = a;
            }
        }
        __syncthreads();
    }
    unsigned long long T = s_T;

    // compact (key, slot) pairs >= T (uniform trips)
    {
        int iters = (S + 255) >> 8;
        for (int it = 0; it < iters; it++) {
            int i = (it << 8) + tid;
            unsigned long long k = (i < S) ? keys[i] : 0ULL;
            bool f = (i < S) && (k >= T);
            unsigned bal = __ballot_sync(0xffffffffu, f);
            int wc = __popc(bal);
            int base = 0;
            if (lane == 0 && wc) base = atomicAdd(&s_cnt, wc);
            base = __shfl_sync(0xffffffffu, base, 0);
            if (f) {
                int pos = base + __popc(bal & ((1u << lane) - 1));
                if (pos < PADF) { s_k2[pos] = k; s_slot[pos] = (short)i; }
            }
        }
    }
    __syncthreads();
    int cf = s_cnt; if (cf > PADF) cf = PADF;
    for (int i = cf + tid; i < PADF; i += blockDim.x) { s_k2[i] = 0ULL; s_slot[i] = 0; }
    __syncthreads();

    // bitonic sort 256 pairs descending by key (1 element per thread)
    for (int k2 = 2; k2 <= PADF; k2 <<= 1) {
        for (int j = k2 >> 1; j > 0; j >>= 1) {
            int i = tid;
            int ixj = i ^ j;
            if (ixj > i && i < PADF) {
                unsigned long long a = s_k2[i];
                unsigned long long d = s_k2[ixj];
                bool desc = ((i & k2) == 0);
                if (desc ? (a < d) : (a > d)) {
                    s_k2[i] = d; s_k2[ixj] = a;
                    short t = s_slot[i]; s_slot[i] = s_slot[ixj]; s_slot[ixj] = t;
                }
            }
            __syncthreads();
        }
    }

    // write output: det_b [B,100,4] | det_s [B,100] | det_l [B,100]
    if (tid < MAXPER) {
        unsigned long long key = s_k2[tid];
        float bx0 = 0.f, bx1 = 0.f, bx2 = 0.f, bx3 = 0.f;
        float sc = 0.f, lb = -1.f;
        if (key != 0ULL) {
            float4 bb = g_sbox[b][s_slot[tid]];
            bx0 = bb.x; bx1 = bb.y; bx2 = bb.z; bx3 = bb.w;
            sc = __uint_as_float((unsigned int)(key >> 32));
            unsigned int idx = 0xFFFFFFFFu - (unsigned int)(key & 0xFFFFFFFFu);
            lb = (float)(idx % CC);
        }
        float* pb = out + ((size_t)b * MAXPER + tid) * 4;
        pb[0] = bx0; pb[1] = bx1; pb[2] = bx2; pb[3] = bx3;
        out[BB * MAXPER * 4 + b * MAXPER + tid] = sc;
        out[BB * MAXPER * 4 + BB * MAXPER + b * MAXPER + tid] = lb;
    }
}

extern "C" void kernel_launch(void* const* d_in, const int* in_sizes, int n_in,
                              void* d_out, int out_size) {
    const float* cls  = (const float*)d_in[0];   // [B,N,81]
    const float* reg  = (const float*)d_in[1];   // [B,N,320]
    const float* rois = (const float*)d_in[2];   // [B,N,4]
    float* out = (float*)d_out;

    k_score<<<(BB * NN * 8) / 256, 256>>>(cls);
    k_thresh<<<BB, 1024>>>();
    k_nms<<<dim3(CC, BB), 128>>>(reg, rois);
    k_final<<<BB, 256>>>(out);
}

// round 7
// speedup vs baseline: 11.2379x; 1.1463x over previous
#include <cuda_runtime.h>
#include <cstdint>

#define BB 4
#define NN 4096
#define CC 80
#define CP1 81
#define KPRE 2000
#define CAP 65536
#define CAPC 1024              // per-class bucket cap
#define NMSCAP 1024            // per-class NMS pool cap
#define PADF 256               // final-stage sort width (>= 100 + bin slack)
#define W_IMG 1333.0f
#define H_IMG 800.0f
#define SCORE_THR 0.05f
#define MAXPER 100
#define MAX_RATIO 4.135166556742356f   // |ln(16/1000)|
#define CLS_OFFSET 1334.0f             // max(H,W)+1

// ---------------- static scratch (no allocations allowed) ----------------
__device__ unsigned long long g_keys[BB][CAP];          // flat candidate keys
__device__ int                g_count[BB];              // reset by k_thresh
__device__ unsigned long long g_ckeys[BB][CC][CAPC];    // per-class buckets
__device__ int                g_ccnt[BB][CC];           // reset by k_nms
__device__ unsigned long long g_T[BB];                  // exact rank-2000 threshold
__device__ unsigned long long g_skey[BB][KPRE];         // survivor keys
__device__ float4             g_sbox[BB][KPRE];         // survivor boxes
__device__ int                g_scnt[BB];               // reset by k_final

// radix level config: 11-bit fields, last level 9 bits (covers all 64 bits)
__device__ __constant__ int c_shift[6] = {53, 42, 31, 20, 9, 0};
__device__ __constant__ int c_width[6] = {11, 11, 11, 11, 11, 9};

// ---- parallel straddle-bin search over s_hist[NB] (blockDim.x == 1024) ----
// finds the unique bin with (above0 + strictly_above_bin) < rank <= ... + h
__device__ __forceinline__ void find_straddle(
    unsigned int* s_hist, int NB, int rank, int above0,
    int* s_bin, int* s_binh, int* s_bincg, unsigned int* s_wtot)
{
    int tid = threadIdx.x, lane = tid & 31, w = tid >> 5;
    int nw = NB >> 6;                        // active warps (64 bins per warp)
    unsigned int h0 = 0, h1 = 0, tsum = 0;
    int b0 = tid * 2;
    if (b0 < NB) { h0 = s_hist[b0]; h1 = s_hist[b0 + 1]; tsum = h0 + h1; }
    unsigned int suf = tsum;                 // warp inclusive suffix of pair sums
    #pragma unroll
    for (int off = 16; off; off >>= 1) {
        unsigned int t = __shfl_down_sync(0xffffffffu, suf, off);
        if (lane + off < 32) suf += t;
    }
    if (lane == 0 && w < nw) s_wtot[w] = suf;
    __syncthreads();
    if (w == 0) {                            // exclusive suffix over warp totals
        unsigned int v = (lane < nw) ? s_wtot[lane] : 0u;
        unsigned int ws = v;
        #pragma unroll
        for (int off = 16; off; off >>= 1) {
            unsigned int t = __shfl_down_sync(0xffffffffu, ws, off);
            if (lane + off < 32) ws += t;
        }
        if (lane < nw) s_wtot[lane] = ws - v;
    }
    __syncthreads();
    if (b0 < NB) {
        unsigned int above_hi = s_wtot[w] + (suf - tsum);   // keys in bins > b0+1
        int a1 = above0 + (int)above_hi;
        int a0 = a1 + (int)h1;
        if (h1 && a1 < rank && a1 + (int)h1 >= rank) { *s_bin = b0 + 1; *s_binh = (int)h1; *s_bincg = a1; }
        if (h0 && a0 < rank && a0 + (int)h0 >= rank) { *s_bin = b0;     *s_binh = (int)h0; *s_bincg = a0; }
    }
    __syncthreads();
}

// ---------------- 1: softmax + threshold + compact + bucket -----------------
__global__ void k_score(const float* __restrict__ cls) {
    int tid = blockIdx.x * blockDim.x + threadIdx.x;
    int row = tid >> 3;
    int o = tid & 7;
    int lane = threadIdx.x & 31;
    if (row >= BB * NN) return;
    int b = row / NN;
    int n = row % NN;
    const float* p = cls + (size_t)row * CP1;

    float v[11];
    #pragma unroll
    for (int k = 0; k < 10; k++) v[k] = p[o + 8 * k];
    v[10] = (o == 0) ? p[80] : -1e30f;

    float m = v[0];
    #pragma unroll
    for (int k = 1; k < 11; k++) m = fmaxf(m, v[k]);
    #pragma unroll
    for (int off = 4; off; off >>= 1) m = fmaxf(m, __shfl_xor_sync(0xffffffffu, m, off));

    float e[11];
    float s = 0.f;
    #pragma unroll
    for (int k = 0; k < 11; k++) { e[k] = expf(v[k] - m); s += e[k]; }
    #pragma unroll
    for (int off = 4; off; off >>= 1) s += __shfl_xor_sync(0xffffffffu, s, off);

    float sc[10];
    int pass = 0, cnt = 0;
    #pragma unroll
    for (int k = 0; k < 10; k++) {
        sc[k] = e[k] / s;
        if (sc[k] > SCORE_THR) { pass |= (1 << k); cnt++; }
    }

    int pre = cnt;
    #pragma unroll
    for (int off = 1; off < 32; off <<= 1) {
        int t = __shfl_up_sync(0xffffffffu, pre, off);
        if (lane >= off) pre += t;
    }
    int excl = pre - cnt;
    int tot = __shfl_sync(0xffffffffu, pre, 31);
    int base = 0;
    if (lane == 0 && tot) base = atomicAdd(&g_count[b], tot);
    base = __shfl_sync(0xffffffffu, base, 0);

    int w = 0;
    #pragma unroll
    for (int k = 0; k < 10; k++) {
        if (pass & (1 << k)) {
            int c = o + 8 * k;
            unsigned int sb = __float_as_uint(sc[k]);
            unsigned int lo = 0xFFFFFFFFu - (unsigned int)(n * CC + c);
            unsigned long long key = ((unsigned long long)sb << 32) | (unsigned long long)lo;
            int pos = base + excl + w; w++;
            if (pos < CAP) g_keys[b][pos] = key;
            int cp = atomicAdd(&g_ccnt[b][c], 1);
            if (cp < CAPC) g_ckeys[b][c][cp] = key;
        }
    }
}

// ---------------- 2: EXACT rank-2000 radix threshold -------------------------
__global__ void k_thresh() {
    __shared__ unsigned int       s_hist[2048];
    __shared__ unsigned int       s_wtot[32];
    __shared__ unsigned long long s_prefix;
    __shared__ int s_above, s_done, s_M;
    __shared__ int s_bin, s_binh, s_bincg;

    int b = blockIdx.x;
    int tid = threadIdx.x;
    const unsigned long long* keys = g_keys[b];

    if (tid == 0) {
        int M = g_count[b]; if (M > CAP) M = CAP;
        s_M = M;
        g_count[b] = 0;
        s_prefix = 0ULL;
        s_above = 0;
        if (M <= KPRE) { g_T[b] = 1ULL; s_done = 1; } else s_done = 0;
    }
    __syncthreads();
    int M = s_M;

    for (int level = 0; level < 6 && !s_done; level++) {
        int shift = c_shift[level];
        int width = c_width[level];
        int NB = 1 << width;
        unsigned long long pmask = (level == 0) ? 0ULL : ((~0ULL) << (shift + width));
        for (int i = tid; i < 2048; i += 1024) s_hist[i] = 0;
        if (tid == 0) s_binh = 0;
        __syncthreads();
        unsigned long long pref = s_prefix;
        for (int i = tid; i < M; i += 1024) {
            unsigned long long k = keys[i];
            if ((k & pmask) == pref)
                atomicAdd(&s_hist[(unsigned int)(k >> shift) & (NB - 1)], 1u);
        }
        __syncthreads();
        find_straddle(s_hist, NB, KPRE, s_above, &s_bin, &s_binh, &s_bincg, s_wtot);
        if (tid == 0) {
            int a = s_bincg, h = s_binh;
            unsigned long long binv = (unsigned long long)s_bin << shift;
            if (h == 0) { s_done = 1; }                       // safety (unreachable)
            else if (a + h == KPRE) { g_T[b] = s_prefix | binv; s_done = 1; }
            else { s_prefix = s_prefix | binv; s_above = a; }
        }
        __syncthreads();
    }
}

// ---------------- 3: per-class NMS, one block per (class, image) -------------
__global__ void k_nms(const float* __restrict__ reg, const float* __restrict__ rois) {
    __shared__ unsigned long long s_k[NMSCAP];
    __shared__ float4             s_bx[NMSCAP];
    __shared__ unsigned char      s_sup[NMSCAP];
    __shared__ short              s_keep[NMSCAP];
    __shared__ int s_cnt, s_n, s_nk, s_base;

    int c = blockIdx.x;
    int b = blockIdx.y;
    int tid = threadIdx.x;
    int lane = tid & 31;

    if (tid == 0) {
        int cc = g_ccnt[b][c]; if (cc > CAPC) cc = CAPC;
        s_cnt = cc;
        g_ccnt[b][c] = 0;
        s_n = 0; s_nk = 0; s_base = 0;
    }
    __syncthreads();
    int cnt = s_cnt;
    unsigned long long T = g_T[b];

    // filter >= T, warp-aggregated append (uniform trips)
    int iters = (cnt + 127) >> 7;
    for (int it = 0; it < iters; it++) {
        int i = (it << 7) + tid;
        unsigned long long k = (i < cnt) ? g_ckeys[b][c][i] : 0ULL;
        bool f = (i < cnt) && (k >= T);
        unsigned bal = __ballot_sync(0xffffffffu, f);
        int wc = __popc(bal);
        int base = 0;
        if (lane == 0 && wc) base = atomicAdd(&s_n, wc);
        base = __shfl_sync(0xffffffffu, base, 0);
        if (f) {
            int pos = base + __popc(bal & ((1u << lane) - 1));
            if (pos < NMSCAP) s_k[pos] = k;
        }
    }
    __syncthreads();
    int n = s_n; if (n > NMSCAP) n = NMSCAP;

    // pad to pow2; warp-0 bitonic sort (descending), __syncwarp only
    int p = 2; while (p < n) p <<= 1;
    for (int i = n + tid; i < p; i += blockDim.x) s_k[i] = 0ULL;
    __syncthreads();
    if (tid < 32) {
        for (int k2 = 2; k2 <= p; k2 <<= 1) {
            for (int j = k2 >> 1; j > 0; j >>= 1) {
                for (int i = lane; i < p; i += 32) {
                    int ixj = i ^ j;
                    if (ixj > i) {
                        unsigned long long a = s_k[i];
                        unsigned long long d = s_k[ixj];
                        bool desc = ((i & k2) == 0);
                        if (desc ? (a < d) : (a > d)) { s_k[i] = d; s_k[ixj] = a; }
                    }
                }
                __syncwarp();
            }
        }
    }
    __syncthreads();

    // decode + clip
    for (int i = tid; i < n; i += blockDim.x) {
        unsigned long long key = s_k[i];
        unsigned int idx = 0xFFFFFFFFu - (unsigned int)(key & 0xFFFFFFFFu);
        int nn = idx / CC;
        const float* r = rois + ((size_t)b * NN + nn) * 4;
        float x1 = r[0], y1 = r[1], x2 = r[2], y2 = r[3];
        float px = (x1 + x2) * 0.5f;
        float py = (y1 + y2) * 0.5f;
        float pw = x2 - x1;
        float ph = y2 - y1;
        const float* d = reg + ((size_t)b * NN + nn) * (4 * CC) + 4 * c;
        float dx = d[0] * 0.1f;
        float dy = d[1] * 0.1f;
        float dw = fminf(d[2] * 0.2f, MAX_RATIO);
        float dh = fminf(d[3] * 0.2f, MAX_RATIO);
        float gx = px + pw * dx;
        float gy = py + ph * dy;
        float gw = pw * expf(dw);
        float gh = ph * expf(dh);
        float bx1 = gx - gw * 0.5f, by1 = gy - gh * 0.5f;
        float bx2 = gx + gw * 0.5f, by2 = gy + gh * 0.5f;
        bx1 = fminf(fmaxf(bx1, 0.f), W_IMG);
        bx2 = fminf(fmaxf(bx2, 0.f), W_IMG);
        by1 = fminf(fmaxf(by1, 0.f), H_IMG);
        by2 = fminf(fmaxf(by2, 0.f), H_IMG);
        s_bx[i] = make_float4(bx1, by1, bx2, by2);
        s_sup[i] = 0;
    }
    __syncthreads();

    // greedy NMS (warp 0); IoU on OFFSET boxes = exact reference arithmetic
    if (tid < 32) {
        float off = (float)c * CLS_OFFSET;
        for (int ii = 0; ii < n; ii++) {
            if (!s_sup[ii]) {
                float4 bi = s_bx[ii];
                bi.x += off; bi.y += off; bi.z += off; bi.w += off;
                float ai = (bi.z - bi.x) * (bi.w - bi.y);
                for (int jj = ii + 1 + lane; jj < n; jj += 32) {
                    float4 bj = s_bx[jj];
                    bj.x += off; bj.y += off; bj.z += off; bj.w += off;
                    float xx1 = fmaxf(bi.x, bj.x);
                    float yy1 = fmaxf(bi.y, bj.y);
                    float xx2 = fminf(bi.z, bj.z);
                    float yy2 = fminf(bi.w, bj.w);
                    float iw = fmaxf(xx2 - xx1, 0.f);
                    float ih = fmaxf(yy2 - yy1, 0.f);
                    float inter = iw * ih;
                    float aj = (bj.z - bj.x) * (bj.w - bj.y);
                    float uni = fmaxf(ai + aj - inter, 1e-6f);
                    if (inter / uni > 0.5f) s_sup[jj] = 1;
                }
            }
            __syncwarp();
        }
        if (lane == 0) {
            int mkeep = 0;
            for (int i = 0; i < n; i++)
                if (!s_sup[i]) s_keep[mkeep++] = (short)i;
            s_nk = mkeep;
            if (mkeep) s_base = atomicAdd(&g_scnt[b], mkeep);
        }
    }
    __syncthreads();
    int nk = s_nk, sb = s_base;
    for (int i = tid; i < nk; i += blockDim.x) {
        int src = s_keep[i];
        g_skey[b][sb + i] = s_k[src];
        g_sbox[b][sb + i] = s_bx[src];
    }
}

// ---------------- 4: top-100 of survivors, ordered output --------------------
__global__ void k_final(float* __restrict__ out) {
    __shared__ unsigned long long s_keys[KPRE];   // survivor keys staged in smem
    __shared__ unsigned int       s_hist[2048];
    __shared__ unsigned int       s_wtot[32];
    __shared__ unsigned long long s_prefix;
    __shared__ unsigned long long s_T;
    __shared__ int s_above, s_done, s_S, s_cnt;
    __shared__ int s_bin, s_binh, s_bincg;
    __shared__ unsigned long long s_k2[PADF];
    __shared__ short              s_slot[PADF];

    int b = blockIdx.x;
    int tid = threadIdx.x;
    int lane = tid & 31;

    if (tid == 0) {
        int S = g_scnt[b]; if (S > KPRE) S = KPRE;
        s_S = S;
        g_scnt[b] = 0;
        s_prefix = 0ULL;
        s_above = 0;
        s_done = (S <= PADF) ? 1 : 0;
        s_T = 1ULL;
        s_cnt = 0;
    }
    __syncthreads();
    int S = s_S;

    for (int i = tid; i < S; i += 1024) s_keys[i] = g_skey[b][i];
    __syncthreads();

    // rank-100 radix with slack (a+h <= PADF); sorted cut below makes it exact
    for (int level = 0; level < 6 && !s_done; level++) {
        int shift = c_shift[level];
        int width = c_width[level];
        int NB = 1 << width;
        unsigned long long pmask = (level == 0) ? 0ULL : ((~0ULL) << (shift + width));
        for (int i = tid; i < 2048; i += 1024) s_hist[i] = 0;
        if (tid == 0) s_binh = 0;
        __syncthreads();
        unsigned long long pref = s_prefix;
        for (int i = tid; i < S; i += 1024) {
            unsigned long long k = s_keys[i];
            if ((k & pmask) == pref)
                atomicAdd(&s_hist[(unsigned int)(k >> shift) & (NB - 1)], 1u);
        }
        __syncthreads();
        find_straddle(s_hist, NB, MAXPER, s_above, &s_bin, &s_binh, &s_bincg, s_wtot);
        if (tid == 0) {
            int a = s_bincg, h = s_binh;
            unsigned long long binv = (unsigned long long)s_bin << shift;
            if (h == 0) { s_done = 1; }
            else if (a + h <= PADF) { s_T = s_prefix | binv; s_done = 1; }
            else { s_prefix = s_prefix | binv; s_above = a; }
        }
        __syncthreads();
    }
    unsigned long long T = s_T;

    // compact (key, slot) pairs >= T (uniform trips)
    {
        int iters = (S + 1023) >> 10;
        for (int it = 0; it < iters; it++) {
            int i = (it << 10) + tid;
            unsigned long long k = (i < S) ? s_keys[i] : 0ULL;
            bool f = (i < S) && (k >= T);
            unsigned bal = __ballot_sync(0xffffffffu, f);
            int wc = __popc(bal);
            int base = 0;
            if (lane == 0 && wc) base = atomicAdd(&s_cnt, wc);
            base = __shfl_sync(0xffffffffu, base, 0);
            if (f) {
                int pos = base + __popc(bal & ((1u << lane) - 1));
                if (pos < PADF) { s_k2[pos] = k; s_slot[pos] = (short)i; }
            }
        }
    }
    __syncthreads();
    int cf = s_cnt; if (cf > PADF) cf = PADF;
    for (int i = cf + tid; i < PADF; i += 1024) { s_k2[i] = 0ULL; s_slot[i] = 0; }
    __syncthreads();

    // hierarchical bitonic sort of 256 pairs, descending by key
    // cross-chunk passes (j>=32): block barriers; j<=16: warp-local (32-elem chunks)
    for (int k2 = 2; k2 <= PADF; k2 <<= 1) {
        for (int j = k2 >> 1; j >= 32; j >>= 1) {
            if (tid < PADF) {
                int i = tid;
                int ixj = i ^ j;
                if (ixj > i) {
                    unsigned long long a = s_k2[i];
                    unsigned long long d = s_k2[ixj];
                    bool desc = ((i & k2) == 0);
                    if (desc ? (a < d) : (a > d)) {
                        s_k2[i] = d; s_k2[ixj] = a;
                        short t = s_slot[i]; s_slot[i] = s_slot[ixj]; s_slot[ixj] = t;
                    }
                }
            }
            __syncthreads();
        }
        if (tid < PADF) {
            int j0 = ((k2 >> 1) < 16) ? (k2 >> 1) : 16;
            for (int j = j0; j >= 1; j >>= 1) {
                int i = tid;
                int ixj = i ^ j;
                if (ixj > i) {
                    unsigned long long a = s_k2[i];
                    unsigned long long d = s_k2[ixj];
                    bool desc = ((i & k2) == 0);
                    if (desc ? (a < d) : (a > d)) {
                        s_k2[i] = d; s_k2[ixj] = a;
                        short t = s_slot[i]; s_slot[i] = s_slot[ixj]; s_slot[ixj] = t;
                    }
                }
                __syncwarp();
            }
        }
        __syncthreads();
    }

    // write output: det_b [B,100,4] | det_s [B,100] | det_l [B,100]
    if (tid < MAXPER) {
        unsigned long long key = s_k2[tid];
        float bx0 = 0.f, bx1 = 0.f, bx2 = 0.f, bx3 = 0.f;
        float sc = 0.f, lb = -1.f;
        if (key != 0ULL) {
            float4 bb = g_sbox[b][s_slot[tid]];
            bx0 = bb.x; bx1 = bb.y; bx2 = bb.z; bx3 = bb.w;
            sc = __uint_as_float((unsigned int)(key >> 32));
            unsigned int idx = 0xFFFFFFFFu - (unsigned int)(key & 0xFFFFFFFFu);
            lb = (float)(idx % CC);
        }
        float* pb = out + ((size_t)b * MAXPER + tid) * 4;
        pb[0] = bx0; pb[1] = bx1; pb[2] = bx2; pb[3] = bx3;
        out[BB * MAXPER * 4 + b * MAXPER + tid] = sc;
        out[BB * MAXPER * 4 + BB * MAXPER + b * MAXPER + tid] = lb;
    }
}

extern "C" void kernel_launch(void* const* d_in, const int* in_sizes, int n_in,
                              void* d_out, int out_size) {
    const float* cls  = (const float*)d_in[0];   // [B,N,81]
    const float* reg  = (const float*)d_in[1];   // [B,N,320]
    const float* rois = (const float*)d_in[2];   // [B,N,4]
    float* out = (float*)d_out;

    k_score<<<(BB * NN * 8) / 256, 256>>>(cls);
    k_thresh<<<BB, 1024>>>();
    k_nms<<<dim3(CC, BB), 128>>>(reg, rois);
    k_final<<<BB, 1024>>>(out);
}